// round 14
// baseline (speedup 1.0000x reference)
#include <cuda_runtime.h>
#include <cuda_fp16.h>
#include <stdint.h>

#define N_NODES  20000
#define N_EDGES  320000
#define F_IN     512
#define F_OUT    1024
#define N_GRAPHS 64

// ---------------- scratch (static device globals; no allocations) ----------
__device__ float g_xw[(size_t)N_NODES * F_OUT];   // gemm1 out, fp16 [N,1024]
__device__ float g_h1[(size_t)N_NODES * F_OUT];   // agg outs, fp16 [N,512]/[N,1024]
__device__ float g_h2[(size_t)N_NODES * F_OUT];   // x fp16 early; gemm2 fp16 late
__device__ float g_w1t[(size_t)F_OUT * F_IN / 2]; // W1^T fp16 [1024,512]
__device__ float g_w2t[(size_t)F_OUT * F_OUT / 2];// W2^T fp16 [1024,1024]
__device__ float g_deg[N_NODES];                  // zero at entry (re-zeroed by pool)
__device__ float g_dinv[N_NODES];
__device__ int   g_cnt_i[N_NODES];                // zero at entry (re-zeroed by pool)
__device__ int   g_rank[N_NODES];
__device__ int   g_ptr[N_NODES + 1];
__device__ int   g_csr_src[N_EDGES];
__device__ float g_csr_norm[N_EDGES];

// ---------------- small helpers ----------------
__device__ __forceinline__ void cp_async16(uint32_t saddr, const void* gptr, bool pred) {
    int sz = pred ? 16 : 0;           // sz=0 -> zero-fill 16B
    asm volatile("cp.async.cg.shared.global [%0], [%1], 16, %2;\n"
                 :: "r"(saddr), "l"(gptr), "r"(sz));
}
#define CP_COMMIT() asm volatile("cp.async.commit_group;\n" ::)
#define CP_WAIT(n)  asm volatile("cp.async.wait_group %0;\n" :: "n"(n))

__device__ __forceinline__ void ldsm_x4(uint32_t& r0, uint32_t& r1, uint32_t& r2,
                                        uint32_t& r3, uint32_t addr) {
    asm volatile("ldmatrix.sync.aligned.m8n8.x4.shared.b16 {%0,%1,%2,%3}, [%4];"
                 : "=r"(r0), "=r"(r1), "=r"(r2), "=r"(r3) : "r"(addr));
}

// ---------------- L1: fused degree-count + x->fp16 convert ----------------
#define EDGE_BLOCKS ((N_EDGES + 255) / 256)               // 1250
#define XCVT4 (N_NODES * F_IN / 4)                        // float4 count
#define XCVT_BLOCKS ((XCVT4 + 255) / 256)                 // 10000

__global__ __launch_bounds__(256)
void k_pre(const int* __restrict__ ei, const float* __restrict__ ew,
           const float* __restrict__ x, __half* __restrict__ xh) {
    int b = blockIdx.x;
    if (b < EDGE_BLOCKS) {
        int e = b * 256 + threadIdx.x;
        if (e < N_EDGES) {
            int d = ei[N_EDGES + e];
            atomicAdd(&g_deg[d], ew[e]);
            atomicAdd(&g_cnt_i[d], 1);
        }
    } else {
        int i = (b - EDGE_BLOCKS) * 256 + threadIdx.x;
        if (i < XCVT4) {
            float4 v = ((const float4*)x)[i];
            __half2 h0 = __floats2half2_rn(v.x, v.y);
            __half2 h1 = __floats2half2_rn(v.z, v.w);
            uint2 p;
            p.x = *reinterpret_cast<uint32_t*>(&h0);
            p.y = *reinterpret_cast<uint32_t*>(&h1);
            ((uint2*)xh)[i] = p;
        }
    }
}

// L2: dinv (+1 self loop) + exclusive prefix sum -> ptr, rank (warp-shuffle)
__global__ __launch_bounds__(1024)
void k_scan() {
    __shared__ int wsum[32];
    const int CH = (N_NODES + 1023) / 1024;  // 20
    int t = threadIdx.x;
    int lane = t & 31;
    int wid  = t >> 5;
    int base = t * CH;

    int s = 0;
    #pragma unroll
    for (int i = 0; i < CH; i++) {
        int idx = base + i;
        if (idx < N_NODES) {
            float d = g_deg[idx] + 1.0f;
            g_dinv[idx] = rsqrtf(d);
            s += g_cnt_i[idx];
        }
    }

    int v = s;
    #pragma unroll
    for (int off = 1; off < 32; off <<= 1) {
        int n = __shfl_up_sync(0xffffffffu, v, off);
        if (lane >= off) v += n;
    }
    if (lane == 31) wsum[wid] = v;
    __syncthreads();
    if (wid == 0) {
        int w = (lane < 32) ? wsum[lane] : 0;
        #pragma unroll
        for (int off = 1; off < 32; off <<= 1) {
            int n = __shfl_up_sync(0xffffffffu, w, off);
            if (lane >= off) w += n;
        }
        wsum[lane] = w;
    }
    __syncthreads();
    int warp_excl = (wid > 0) ? wsum[wid - 1] : 0;
    int run = warp_excl + v - s;

    #pragma unroll
    for (int i = 0; i < CH; i++) {
        int idx = base + i;
        if (idx < N_NODES) { g_ptr[idx] = run; g_rank[idx] = run; run += g_cnt_i[idx]; }
    }
    if (t == 1023) g_ptr[N_NODES] = run;
}

// L3: CSR scatter
__global__ void k_scatter(const int* __restrict__ ei, const float* __restrict__ ew) {
    int e = blockIdx.x * blockDim.x + threadIdx.x;
    if (e < N_EDGES) {
        int s = ei[e];
        int d = ei[N_EDGES + e];
        int pos = atomicAdd(&g_rank[d], 1);
        g_csr_src[pos]  = s;
        g_csr_norm[pos] = g_dinv[s] * ew[e] * g_dinv[d];
    }
}

// ---------------- fused CSR aggregation, fp16 in -> fp16 out --------------
template<int F>
__global__ __launch_bounds__(F / 4)
void k_agg_h(const __half* __restrict__ in, __half* __restrict__ out) {
    int n = blockIdx.x;
    int f = threadIdx.x * 4;

    float di = g_dinv[n];
    float s = di * di;

    uint2 raw = *(const uint2*)(in + (size_t)n * F + f);
    float2 p0 = __half22float2(*reinterpret_cast<__half2*>(&raw.x));
    float2 p1 = __half22float2(*reinterpret_cast<__half2*>(&raw.y));
    float4 acc = make_float4(s * p0.x, s * p0.y, s * p1.x, s * p1.y);

    int e0 = g_ptr[n], e1 = g_ptr[n + 1];
    for (int e = e0; e < e1; e++) {
        int src = __ldg(&g_csr_src[e]);
        float w = __ldg(&g_csr_norm[e]);
        uint2 r = *(const uint2*)(in + (size_t)src * F + f);
        float2 u0 = __half22float2(*reinterpret_cast<__half2*>(&r.x));
        float2 u1 = __half22float2(*reinterpret_cast<__half2*>(&r.y));
        acc.x = fmaf(w, u0.x, acc.x);
        acc.y = fmaf(w, u0.y, acc.y);
        acc.z = fmaf(w, u1.x, acc.z);
        acc.w = fmaf(w, u1.y, acc.w);
    }
    __half2 o0 = __floats2half2_rn(acc.x, acc.y);
    __half2 o1 = __floats2half2_rn(acc.z, acc.w);
    uint2 p;
    p.x = *reinterpret_cast<uint32_t*>(&o0);
    p.y = *reinterpret_cast<uint32_t*>(&o1);
    *(uint2*)(out + (size_t)n * F + f) = p;
}

// ---------------- weight transposes (fp32 -> fp16) ----------------
__device__ __forceinline__ void tr_tile(const float* __restrict__ W,
                                        __half* __restrict__ Wt, int R, int C) {
    __shared__ float s[32][33];
    int x  = blockIdx.x * 32 + threadIdx.x;
    int y0 = blockIdx.y * 32;
    #pragma unroll
    for (int i = 0; i < 32; i += 8)
        s[threadIdx.y + i][threadIdx.x] = W[(size_t)(y0 + threadIdx.y + i) * C + x];
    __syncthreads();
    int xt  = blockIdx.y * 32 + threadIdx.x;
    int yt0 = blockIdx.x * 32;
    #pragma unroll
    for (int i = 0; i < 32; i += 8)
        Wt[(size_t)(yt0 + threadIdx.y + i) * R + xt] = __float2half_rn(s[threadIdx.x][threadIdx.y + i]);
}

__global__ __launch_bounds__(256)
void k_tr2(const float* __restrict__ W1, __half* __restrict__ W1t,
           const float* __restrict__ W2, __half* __restrict__ W2t) {
    if (blockIdx.z == 0) {
        if (blockIdx.y < F_IN / 32) tr_tile(W1, W1t, F_IN, F_OUT);
    } else {
        tr_tile(W2, W2t, F_OUT, F_OUT);
    }
}

// ---------------- fp16 mma.sync GEMM, 128x128, BK=32, 4 warps, 3 CTAs/SM -
#define BM 128
#define BN 128
#define BKH 32                                // K halfs per stage
#define PADH 40                               // halfs per smem row (80B)
#define A_STG (BM * PADH)                     // 5120 halfs
#define B_STG (BN * PADH)
#define GEMM_SMEM (3 * (A_STG + B_STG) * 2)   // 61440 B

__device__ __forceinline__ void mma_f16(float c[4], const uint32_t a[4],
                                        uint32_t b0, uint32_t b1) {
    asm volatile(
        "mma.sync.aligned.m16n8k16.row.col.f32.f16.f16.f32 "
        "{%0,%1,%2,%3}, {%4,%5,%6,%7}, {%8,%9}, {%0,%1,%2,%3};"
        : "+f"(c[0]), "+f"(c[1]), "+f"(c[2]), "+f"(c[3])
        : "r"(a[0]), "r"(a[1]), "r"(a[2]), "r"(a[3]), "r"(b0), "r"(b1));
}

template<typename OT>
__global__ __launch_bounds__(128, 3)
void k_gemm(const __half* __restrict__ A, const __half* __restrict__ Bt,
            OT* __restrict__ C, const float* __restrict__ bias, int M, int K) {
    extern __shared__ __half smem[];

    const int tid  = threadIdx.x;
    const int lane = tid & 31;
    const int warp = tid >> 5;
    const int wm = warp & 1;
    const int wn = warp >> 1;
    const int g = lane >> 2;
    const int t = lane & 3;

    const int brow = blockIdx.y * BM;
    const int bcol = blockIdx.x * BN;
    const int rmaxA = M - brow;

    uint32_t sbase = (uint32_t)__cvta_generic_to_shared(smem);
    uint32_t sA[3], sB[3];
    #pragma unroll
    for (int s = 0; s < 3; s++) {
        sA[s] = sbase + (uint32_t)(s * (A_STG + B_STG)) * 2;
        sB[s] = sA[s] + A_STG * 2;
    }

    const __half* Ag = A + (size_t)brow * K;
    const __half* Bg = Bt + (size_t)bcol * K;

    const int la_row = wm * 64 + ((lane >> 3) & 1) * 8 + (lane & 7);
    const int la_col = ((lane >> 4) & 1) * 8;   // halfs
    const int lb_row = wn * 64 + ((lane >> 4) & 1) * 8 + (lane & 7);
    const int lb_col = ((lane >> 3) & 1) * 8;   // halfs

    const int KT = K >> 5;   // k-tiles of 32 halfs

    // fill: A and B each 128 rows x 4 16B-chunks = 512 chunks, 4/thread
    #define FILL(st, kt_) do {                                                  \
        int k0_ = (kt_) * BKH;                                                  \
        _Pragma("unroll")                                                       \
        for (int u_ = 0; u_ < 4; u_++) {                                        \
            int ch_ = tid + u_ * 128;                                           \
            int r_ = ch_ >> 2, c_ = ch_ & 3;                                    \
            cp_async16(sA[st] + (r_ * PADH + c_ * 8) * 2,                       \
                       Ag + (size_t)r_ * K + k0_ + c_ * 8, r_ < rmaxA);         \
            cp_async16(sB[st] + (r_ * PADH + c_ * 8) * 2,                       \
                       Bg + (size_t)r_ * K + k0_ + c_ * 8, true);               \
        }                                                                       \
        CP_COMMIT();                                                            \
    } while (0)

    FILL(0, 0);
    FILL(1, 1);

    float acc[4][8][4];
    #pragma unroll
    for (int i = 0; i < 4; i++)
        #pragma unroll
        for (int j = 0; j < 8; j++)
            #pragma unroll
            for (int r = 0; r < 4; r++) acc[i][j][r] = 0.0f;

    for (int kt = 0; kt < KT; kt++) {
        if (kt + 1 < KT) { CP_WAIT(1); } else { CP_WAIT(0); }
        __syncthreads();

        // hoist next fill: stage (kt+2)%3 == (kt-1)%3, free after the barrier
        if (kt + 2 < KT) {
            int nb = (kt + 2) % 3;
            FILL(nb, kt + 2);
        }

        int buf = kt % 3;
        uint32_t aab = sA[buf] + (la_row * PADH + la_col) * 2;
        uint32_t bab = sB[buf] + (lb_row * PADH + lb_col) * 2;

        #pragma unroll
        for (int ks = 0; ks < 2; ks++) {
            const int kb = ks * 16;   // halfs
            uint32_t af[4][4];
            #pragma unroll
            for (int i = 0; i < 4; i++)
                ldsm_x4(af[i][0], af[i][1], af[i][2], af[i][3],
                        aab + (i * 16 * PADH + kb) * 2);
            uint32_t bf[4][4];
            #pragma unroll
            for (int j2 = 0; j2 < 4; j2++)
                ldsm_x4(bf[j2][0], bf[j2][1], bf[j2][2], bf[j2][3],
                        bab + (j2 * 16 * PADH + kb) * 2);
            #pragma unroll
            for (int i = 0; i < 4; i++) {
                #pragma unroll
                for (int j = 0; j < 8; j++) {
                    const uint32_t* bp = &bf[j >> 1][(j & 1) * 2];
                    mma_f16(acc[i][j], af[i], bp[0], bp[1]);
                }
            }
        }
    }
    #undef FILL

    // epilogue: bias + relu; fp32 or fp16 store
    #pragma unroll
    for (int j = 0; j < 8; j++) {
        int c0 = bcol + wn * 64 + j * 8 + 2 * t;
        float2 bb = *(const float2*)(bias + c0);
        #pragma unroll
        for (int i = 0; i < 4; i++) {
            int r0 = brow + wm * 64 + i * 16 + g;
            int r1 = r0 + 8;
            float2 v0 = make_float2(fmaxf(acc[i][j][0] + bb.x, 0.0f),
                                    fmaxf(acc[i][j][1] + bb.y, 0.0f));
            float2 v1 = make_float2(fmaxf(acc[i][j][2] + bb.x, 0.0f),
                                    fmaxf(acc[i][j][3] + bb.y, 0.0f));
            if constexpr (sizeof(OT) == 2) {
                if (r0 < M) {
                    __half2 h = __floats2half2_rn(v0.x, v0.y);
                    *(uint32_t*)((__half*)C + (size_t)r0 * F_OUT + c0) =
                        *reinterpret_cast<uint32_t*>(&h);
                }
                if (r1 < M) {
                    __half2 h = __floats2half2_rn(v1.x, v1.y);
                    *(uint32_t*)((__half*)C + (size_t)r1 * F_OUT + c0) =
                        *reinterpret_cast<uint32_t*>(&h);
                }
            } else {
                if (r0 < M) *(float2*)((float*)C + (size_t)r0 * F_OUT + c0) = v0;
                if (r1 < M) *(float2*)((float*)C + (size_t)r1 * F_OUT + c0) = v1;
            }
        }
    }
}

// ---------------- segmented mean pooling (fp16 in) + re-zero deg/cnt -----
__global__ __launch_bounds__(64)
void k_pool(const int* __restrict__ batch, const __half* __restrict__ h,
            float* __restrict__ out) {
    int gph = blockIdx.y;
    int f = blockIdx.x * 256 + threadIdx.x * 4;

    int gt = (blockIdx.y * gridDim.x + blockIdx.x) * 64 + threadIdx.x;
    for (int i = gt; i < N_NODES; i += 16384) { g_deg[i] = 0.0f; g_cnt_i[i] = 0; }

    int lo = 0, hi = N_NODES;
    while (lo < hi) { int m = (lo + hi) >> 1; if (batch[m] < gph) lo = m + 1; else hi = m; }
    int s = lo;
    hi = N_NODES;
    while (lo < hi) { int m = (lo + hi) >> 1; if (batch[m] < gph + 1) lo = m + 1; else hi = m; }
    int e = lo;

    float4 acc = make_float4(0.f, 0.f, 0.f, 0.f);
    for (int n = s; n < e; n++) {
        uint2 r = *(const uint2*)(h + (size_t)n * F_OUT + f);
        float2 u0 = __half22float2(*reinterpret_cast<__half2*>(&r.x));
        float2 u1 = __half22float2(*reinterpret_cast<__half2*>(&r.y));
        acc.x += u0.x; acc.y += u0.y; acc.z += u1.x; acc.w += u1.y;
    }
    float c = 1.0f / fmaxf((float)(e - s), 1.0f);
    acc.x *= c; acc.y *= c; acc.z *= c; acc.w *= c;
    *(float4*)(out + (size_t)gph * F_OUT + f) = acc;
}

// ---------------- launch ----------------
extern "C" void kernel_launch(void* const* d_in, const int* in_sizes, int n_in,
                              void* d_out, int out_size) {
    const float* x     = (const float*)d_in[0];
    const int*   ei    = (const int*)d_in[1];
    const float* ew    = (const float*)d_in[2];
    const int*   batch = (const int*)d_in[3];
    const float* W1    = (const float*)d_in[4];
    const float* b1    = (const float*)d_in[5];
    const float* W2    = (const float*)d_in[6];
    const float* b2    = (const float*)d_in[7];
    float* out = (float*)d_out;

    float *xw, *h1, *h2, *w1t, *w2t;
    cudaGetSymbolAddress((void**)&xw,  g_xw);
    cudaGetSymbolAddress((void**)&h1,  g_h1);
    cudaGetSymbolAddress((void**)&h2,  g_h2);
    cudaGetSymbolAddress((void**)&w1t, g_w1t);
    cudaGetSymbolAddress((void**)&w2t, g_w2t);

    __half* xh    = (__half*)h2;
    __half* aggh  = (__half*)h1;
    __half* xw_h  = (__half*)xw;
    __half* h2h   = (__half*)h2;     // gemm2 fp16 output (xh dead by then)
    __half* w1th  = (__half*)w1t;
    __half* w2th  = (__half*)w2t;

    static int smem_set = 0;
    if (!smem_set) {
        cudaFuncSetAttribute(k_gemm<__half>,
                             cudaFuncAttributeMaxDynamicSharedMemorySize, GEMM_SMEM);
        smem_set = 1;
    }

    const int T = 256;
    dim3 gg(F_OUT / BN, (N_NODES + BM - 1) / BM);

    // L1: fused deg-count + x->fp16
    k_pre<<<EDGE_BLOCKS + XCVT_BLOCKS, T>>>(ei, ew, x, xh);
    // L2: dinv + warp-shuffle scan
    k_scan<<<1, 1024>>>();
    // L3: CSR scatter
    k_scatter<<<(N_EDGES + T - 1) / T, T>>>(ei, ew);
    // L4: layer-1 aggregation (fp16 -> fp16)
    k_agg_h<F_IN><<<N_NODES, F_IN / 4>>>(xh, aggh);
    // L5: weight transposes (fp32 -> fp16)
    k_tr2<<<dim3(F_OUT / 32, F_OUT / 32, 2), dim3(32, 8)>>>(W1, w1th, W2, w2th);
    // L6: gemm1 (fp16 mma, 3 CTAs/SM) -> fp16 xw, bias+relu fused
    k_gemm<__half><<<gg, 128, GEMM_SMEM>>>(aggh, w1th, xw_h, b1, N_NODES, F_IN);
    // L7: layer-2 aggregation (fp16 -> fp16)
    k_agg_h<F_OUT><<<N_NODES, F_OUT / 4>>>(xw_h, aggh);
    // L8: gemm2 (fp16 mma, 3 CTAs/SM) -> fp16 h2, bias+relu fused
    k_gemm<__half><<<gg, 128, GEMM_SMEM>>>(aggh, w2th, h2h, b2, N_NODES, F_OUT);
    // L9: mean pool (fp16 in) + re-zero deg/cnt
    k_pool<<<dim3(4, N_GRAPHS), 64>>>(batch, h2h, out);
}

// round 15
// speedup vs baseline: 1.0158x; 1.0158x over previous
#include <cuda_runtime.h>
#include <cuda_fp16.h>
#include <stdint.h>

#define N_NODES  20000
#define N_EDGES  320000
#define F_IN     512
#define F_OUT    1024
#define N_GRAPHS 64

// ---------------- scratch (static device globals; no allocations) ----------
__device__ float g_xw[(size_t)N_NODES * F_OUT];   // gemm1 out, fp16 [N,1024]
__device__ float g_h1[(size_t)N_NODES * F_OUT];   // agg outs, fp16 [N,512]/[N,1024]
__device__ float g_h2[(size_t)N_NODES * F_OUT];   // x fp16 early; gemm2 fp16 late
__device__ float g_w1t[(size_t)F_OUT * F_IN / 2]; // W1^T fp16 [1024,512]
__device__ float g_w2t[(size_t)F_OUT * F_OUT / 2];// W2^T fp16 [1024,1024]
__device__ float g_deg[N_NODES];                  // zero at entry (re-zeroed by pool)
__device__ float g_dinv[N_NODES];
__device__ int   g_cnt_i[N_NODES];                // zero at entry (re-zeroed by pool)
__device__ int   g_rank[N_NODES];
__device__ int   g_ptr[N_NODES + 1];
__device__ int   g_csr_src[N_EDGES];
__device__ float g_csr_norm[N_EDGES];

// ---------------- small helpers ----------------
__device__ __forceinline__ void cp_async16(uint32_t saddr, const void* gptr, bool pred) {
    int sz = pred ? 16 : 0;           // sz=0 -> zero-fill 16B
    asm volatile("cp.async.cg.shared.global [%0], [%1], 16, %2;\n"
                 :: "r"(saddr), "l"(gptr), "r"(sz));
}
#define CP_COMMIT() asm volatile("cp.async.commit_group;\n" ::)
#define CP_WAIT(n)  asm volatile("cp.async.wait_group %0;\n" :: "n"(n))

__device__ __forceinline__ void ldsm_x4(uint32_t& r0, uint32_t& r1, uint32_t& r2,
                                        uint32_t& r3, uint32_t addr) {
    asm volatile("ldmatrix.sync.aligned.m8n8.x4.shared.b16 {%0,%1,%2,%3}, [%4];"
                 : "=r"(r0), "=r"(r1), "=r"(r2), "=r"(r3) : "r"(addr));
}

// ---------------- L1: fused degree-count + x->fp16 convert ----------------
#define EDGE_BLOCKS ((N_EDGES + 255) / 256)               // 1250
#define XCVT4 (N_NODES * F_IN / 4)                        // float4 count
#define XCVT_BLOCKS ((XCVT4 + 255) / 256)                 // 10000

__global__ __launch_bounds__(256)
void k_pre(const int* __restrict__ ei, const float* __restrict__ ew,
           const float* __restrict__ x, __half* __restrict__ xh) {
    int b = blockIdx.x;
    if (b < EDGE_BLOCKS) {
        int e = b * 256 + threadIdx.x;
        if (e < N_EDGES) {
            int d = ei[N_EDGES + e];
            atomicAdd(&g_deg[d], ew[e]);
            atomicAdd(&g_cnt_i[d], 1);
        }
    } else {
        int i = (b - EDGE_BLOCKS) * 256 + threadIdx.x;
        if (i < XCVT4) {
            float4 v = ((const float4*)x)[i];
            __half2 h0 = __floats2half2_rn(v.x, v.y);
            __half2 h1 = __floats2half2_rn(v.z, v.w);
            uint2 p;
            p.x = *reinterpret_cast<uint32_t*>(&h0);
            p.y = *reinterpret_cast<uint32_t*>(&h1);
            ((uint2*)xh)[i] = p;
        }
    }
}

// L2: dinv (+1 self loop) + exclusive prefix sum -> ptr, rank (warp-shuffle)
__global__ __launch_bounds__(1024)
void k_scan() {
    __shared__ int wsum[32];
    const int CH = (N_NODES + 1023) / 1024;  // 20
    int t = threadIdx.x;
    int lane = t & 31;
    int wid  = t >> 5;
    int base = t * CH;

    int s = 0;
    #pragma unroll
    for (int i = 0; i < CH; i++) {
        int idx = base + i;
        if (idx < N_NODES) {
            float d = g_deg[idx] + 1.0f;
            g_dinv[idx] = rsqrtf(d);
            s += g_cnt_i[idx];
        }
    }

    int v = s;
    #pragma unroll
    for (int off = 1; off < 32; off <<= 1) {
        int n = __shfl_up_sync(0xffffffffu, v, off);
        if (lane >= off) v += n;
    }
    if (lane == 31) wsum[wid] = v;
    __syncthreads();
    if (wid == 0) {
        int w = (lane < 32) ? wsum[lane] : 0;
        #pragma unroll
        for (int off = 1; off < 32; off <<= 1) {
            int n = __shfl_up_sync(0xffffffffu, w, off);
            if (lane >= off) w += n;
        }
        wsum[lane] = w;
    }
    __syncthreads();
    int warp_excl = (wid > 0) ? wsum[wid - 1] : 0;
    int run = warp_excl + v - s;

    #pragma unroll
    for (int i = 0; i < CH; i++) {
        int idx = base + i;
        if (idx < N_NODES) { g_ptr[idx] = run; g_rank[idx] = run; run += g_cnt_i[idx]; }
    }
    if (t == 1023) g_ptr[N_NODES] = run;
}

// L3: CSR scatter
__global__ void k_scatter(const int* __restrict__ ei, const float* __restrict__ ew) {
    int e = blockIdx.x * blockDim.x + threadIdx.x;
    if (e < N_EDGES) {
        int s = ei[e];
        int d = ei[N_EDGES + e];
        int pos = atomicAdd(&g_rank[d], 1);
        g_csr_src[pos]  = s;
        g_csr_norm[pos] = g_dinv[s] * ew[e] * g_dinv[d];
    }
}

// ---------------- fused CSR aggregation, fp16 in -> fp16 out --------------
template<int F>
__global__ __launch_bounds__(F / 4)
void k_agg_h(const __half* __restrict__ in, __half* __restrict__ out) {
    int n = blockIdx.x;
    int f = threadIdx.x * 4;

    float di = g_dinv[n];
    float s = di * di;

    uint2 raw = *(const uint2*)(in + (size_t)n * F + f);
    float2 p0 = __half22float2(*reinterpret_cast<__half2*>(&raw.x));
    float2 p1 = __half22float2(*reinterpret_cast<__half2*>(&raw.y));
    float4 acc = make_float4(s * p0.x, s * p0.y, s * p1.x, s * p1.y);

    int e0 = g_ptr[n], e1 = g_ptr[n + 1];
    for (int e = e0; e < e1; e++) {
        int src = __ldg(&g_csr_src[e]);
        float w = __ldg(&g_csr_norm[e]);
        uint2 r = *(const uint2*)(in + (size_t)src * F + f);
        float2 u0 = __half22float2(*reinterpret_cast<__half2*>(&r.x));
        float2 u1 = __half22float2(*reinterpret_cast<__half2*>(&r.y));
        acc.x = fmaf(w, u0.x, acc.x);
        acc.y = fmaf(w, u0.y, acc.y);
        acc.z = fmaf(w, u1.x, acc.z);
        acc.w = fmaf(w, u1.y, acc.w);
    }
    __half2 o0 = __floats2half2_rn(acc.x, acc.y);
    __half2 o1 = __floats2half2_rn(acc.z, acc.w);
    uint2 p;
    p.x = *reinterpret_cast<uint32_t*>(&o0);
    p.y = *reinterpret_cast<uint32_t*>(&o1);
    *(uint2*)(out + (size_t)n * F + f) = p;
}

// ---------------- weight transposes (fp32 -> fp16) ----------------
__device__ __forceinline__ void tr_tile(const float* __restrict__ W,
                                        __half* __restrict__ Wt, int R, int C) {
    __shared__ float s[32][33];
    int x  = blockIdx.x * 32 + threadIdx.x;
    int y0 = blockIdx.y * 32;
    #pragma unroll
    for (int i = 0; i < 32; i += 8)
        s[threadIdx.y + i][threadIdx.x] = W[(size_t)(y0 + threadIdx.y + i) * C + x];
    __syncthreads();
    int xt  = blockIdx.y * 32 + threadIdx.x;
    int yt0 = blockIdx.x * 32;
    #pragma unroll
    for (int i = 0; i < 32; i += 8)
        Wt[(size_t)(yt0 + threadIdx.y + i) * R + xt] = __float2half_rn(s[threadIdx.x][threadIdx.y + i]);
}

__global__ __launch_bounds__(256)
void k_tr2(const float* __restrict__ W1, __half* __restrict__ W1t,
           const float* __restrict__ W2, __half* __restrict__ W2t) {
    if (blockIdx.z == 0) {
        if (blockIdx.y < F_IN / 32) tr_tile(W1, W1t, F_IN, F_OUT);
    } else {
        tr_tile(W2, W2t, F_OUT, F_OUT);
    }
}

// ---------------- fp16 mma.sync GEMM, 128x128, BK=64, 8 warps 2x4 --------
// C = relu(A @ W + bias); A fp16 [M,K], Bt = W^T fp16 [1024,K] row-major.
// m16n8k16, warp tile 64x32, 3-stage cp.async, 2 CTAs/SM, 16 warps/SM.
#define BM 128
#define BN 128
#define BKH 64                                // K halfs per stage
#define PADH 72                               // halfs per smem row (144B)
#define A_STG (BM * PADH)
#define B_STG (BN * PADH)
#define GEMM_SMEM (3 * (A_STG + B_STG) * 2)   // 110592 B

__device__ __forceinline__ void mma_f16(float c[4], const uint32_t a[4],
                                        uint32_t b0, uint32_t b1) {
    asm volatile(
        "mma.sync.aligned.m16n8k16.row.col.f32.f16.f16.f32 "
        "{%0,%1,%2,%3}, {%4,%5,%6,%7}, {%8,%9}, {%0,%1,%2,%3};"
        : "+f"(c[0]), "+f"(c[1]), "+f"(c[2]), "+f"(c[3])
        : "r"(a[0]), "r"(a[1]), "r"(a[2]), "r"(a[3]), "r"(b0), "r"(b1));
}

template<typename OT>
__global__ __launch_bounds__(256, 2)
void k_gemm(const __half* __restrict__ A, const __half* __restrict__ Bt,
            OT* __restrict__ C, const float* __restrict__ bias, int M, int K) {
    extern __shared__ __half smem[];

    const int tid  = threadIdx.x;
    const int lane = tid & 31;
    const int warp = tid >> 5;    // 0..7
    const int wm = warp & 1;      // 2 m-warps (64 rows each)
    const int wn = warp >> 1;     // 4 n-warps (32 cols each)
    const int g = lane >> 2;
    const int t = lane & 3;

    const int brow = blockIdx.y * BM;
    const int bcol = blockIdx.x * BN;
    const int rmaxA = M - brow;

    uint32_t sbase = (uint32_t)__cvta_generic_to_shared(smem);
    uint32_t sA[3], sB[3];
    #pragma unroll
    for (int s = 0; s < 3; s++) {
        sA[s] = sbase + (uint32_t)(s * (A_STG + B_STG)) * 2;
        sB[s] = sA[s] + A_STG * 2;
    }

    const __half* Ag = A + (size_t)brow * K;
    const __half* Bg = Bt + (size_t)bcol * K;

    // ldmatrix lane addressing (16B col units = 8 halfs); warp tile 64x32
    const int la_row = wm * 64 + ((lane >> 3) & 1) * 8 + (lane & 7);
    const int la_col = ((lane >> 4) & 1) * 8;   // halfs
    const int lb_row = wn * 32 + ((lane >> 4) & 1) * 8 + (lane & 7);
    const int lb_col = ((lane >> 3) & 1) * 8;   // halfs

    const int KT = K >> 6;   // k-tiles of 64 halfs

    // fill: A and B each 128 rows x 8 16B-chunks = 1024 chunks, 4/thread
    #define FILL(st, kt_) do {                                                  \
        int k0_ = (kt_) * BKH;                                                  \
        _Pragma("unroll")                                                       \
        for (int u_ = 0; u_ < 4; u_++) {                                        \
            int ch_ = tid + u_ * 256;                                           \
            int r_ = ch_ >> 3, c_ = ch_ & 7;                                    \
            cp_async16(sA[st] + (r_ * PADH + c_ * 8) * 2,                       \
                       Ag + (size_t)r_ * K + k0_ + c_ * 8, r_ < rmaxA);         \
            cp_async16(sB[st] + (r_ * PADH + c_ * 8) * 2,                       \
                       Bg + (size_t)r_ * K + k0_ + c_ * 8, true);               \
        }                                                                       \
        CP_COMMIT();                                                            \
    } while (0)

    FILL(0, 0);
    FILL(1, 1);

    float acc[4][4][4];
    #pragma unroll
    for (int i = 0; i < 4; i++)
        #pragma unroll
        for (int j = 0; j < 4; j++)
            #pragma unroll
            for (int r = 0; r < 4; r++) acc[i][j][r] = 0.0f;

    for (int kt = 0; kt < KT; kt++) {
        if (kt + 1 < KT) { CP_WAIT(1); } else { CP_WAIT(0); }
        __syncthreads();

        // hoist next fill: stage (kt+2)%3 == (kt-1)%3, free after the barrier
        if (kt + 2 < KT) {
            int nb = (kt + 2) % 3;
            FILL(nb, kt + 2);
        }

        int buf = kt % 3;
        uint32_t aab = sA[buf] + (la_row * PADH + la_col) * 2;
        uint32_t bab = sB[buf] + (lb_row * PADH + lb_col) * 2;

        #pragma unroll
        for (int ks = 0; ks < 4; ks++) {
            const int kb = ks * 16;   // halfs
            uint32_t af[4][4];
            #pragma unroll
            for (int i = 0; i < 4; i++)
                ldsm_x4(af[i][0], af[i][1], af[i][2], af[i][3],
                        aab + (i * 16 * PADH + kb) * 2);
            uint32_t bf[2][4];
            #pragma unroll
            for (int j2 = 0; j2 < 2; j2++)
                ldsm_x4(bf[j2][0], bf[j2][1], bf[j2][2], bf[j2][3],
                        bab + (j2 * 16 * PADH + kb) * 2);
            #pragma unroll
            for (int i = 0; i < 4; i++) {
                #pragma unroll
                for (int j = 0; j < 4; j++) {
                    const uint32_t* bp = &bf[j >> 1][(j & 1) * 2];
                    mma_f16(acc[i][j], af[i], bp[0], bp[1]);
                }
            }
        }
    }
    #undef FILL

    // epilogue: bias + relu; fp32 or fp16 store
    #pragma unroll
    for (int j = 0; j < 4; j++) {
        int c0 = bcol + wn * 32 + j * 8 + 2 * t;
        float2 bb = *(const float2*)(bias + c0);
        #pragma unroll
        for (int i = 0; i < 4; i++) {
            int r0 = brow + wm * 64 + i * 16 + g;
            int r1 = r0 + 8;
            float2 v0 = make_float2(fmaxf(acc[i][j][0] + bb.x, 0.0f),
                                    fmaxf(acc[i][j][1] + bb.y, 0.0f));
            float2 v1 = make_float2(fmaxf(acc[i][j][2] + bb.x, 0.0f),
                                    fmaxf(acc[i][j][3] + bb.y, 0.0f));
            if constexpr (sizeof(OT) == 2) {
                if (r0 < M) {
                    __half2 h = __floats2half2_rn(v0.x, v0.y);
                    *(uint32_t*)((__half*)C + (size_t)r0 * F_OUT + c0) =
                        *reinterpret_cast<uint32_t*>(&h);
                }
                if (r1 < M) {
                    __half2 h = __floats2half2_rn(v1.x, v1.y);
                    *(uint32_t*)((__half*)C + (size_t)r1 * F_OUT + c0) =
                        *reinterpret_cast<uint32_t*>(&h);
                }
            } else {
                if (r0 < M) *(float2*)((float*)C + (size_t)r0 * F_OUT + c0) = v0;
                if (r1 < M) *(float2*)((float*)C + (size_t)r1 * F_OUT + c0) = v1;
            }
        }
    }
}

// ---------------- segmented mean pooling (fp16 in) + re-zero deg/cnt -----
__global__ __launch_bounds__(64)
void k_pool(const int* __restrict__ batch, const __half* __restrict__ h,
            float* __restrict__ out) {
    int gph = blockIdx.y;
    int f = blockIdx.x * 256 + threadIdx.x * 4;

    int gt = (blockIdx.y * gridDim.x + blockIdx.x) * 64 + threadIdx.x;
    for (int i = gt; i < N_NODES; i += 16384) { g_deg[i] = 0.0f; g_cnt_i[i] = 0; }

    int lo = 0, hi = N_NODES;
    while (lo < hi) { int m = (lo + hi) >> 1; if (batch[m] < gph) lo = m + 1; else hi = m; }
    int s = lo;
    hi = N_NODES;
    while (lo < hi) { int m = (lo + hi) >> 1; if (batch[m] < gph + 1) lo = m + 1; else hi = m; }
    int e = lo;

    float4 acc = make_float4(0.f, 0.f, 0.f, 0.f);
    for (int n = s; n < e; n++) {
        uint2 r = *(const uint2*)(h + (size_t)n * F_OUT + f);
        float2 u0 = __half22float2(*reinterpret_cast<__half2*>(&r.x));
        float2 u1 = __half22float2(*reinterpret_cast<__half2*>(&r.y));
        acc.x += u0.x; acc.y += u0.y; acc.z += u1.x; acc.w += u1.y;
    }
    float c = 1.0f / fmaxf((float)(e - s), 1.0f);
    acc.x *= c; acc.y *= c; acc.z *= c; acc.w *= c;
    *(float4*)(out + (size_t)gph * F_OUT + f) = acc;
}

// ---------------- launch ----------------
extern "C" void kernel_launch(void* const* d_in, const int* in_sizes, int n_in,
                              void* d_out, int out_size) {
    const float* x     = (const float*)d_in[0];
    const int*   ei    = (const int*)d_in[1];
    const float* ew    = (const float*)d_in[2];
    const int*   batch = (const int*)d_in[3];
    const float* W1    = (const float*)d_in[4];
    const float* b1    = (const float*)d_in[5];
    const float* W2    = (const float*)d_in[6];
    const float* b2    = (const float*)d_in[7];
    float* out = (float*)d_out;

    float *xw, *h1, *h2, *w1t, *w2t;
    cudaGetSymbolAddress((void**)&xw,  g_xw);
    cudaGetSymbolAddress((void**)&h1,  g_h1);
    cudaGetSymbolAddress((void**)&h2,  g_h2);
    cudaGetSymbolAddress((void**)&w1t, g_w1t);
    cudaGetSymbolAddress((void**)&w2t, g_w2t);

    __half* xh    = (__half*)h2;
    __half* aggh  = (__half*)h1;
    __half* xw_h  = (__half*)xw;
    __half* h2h   = (__half*)h2;     // gemm2 fp16 output (xh dead by then)
    __half* w1th  = (__half*)w1t;
    __half* w2th  = (__half*)w2t;

    static int smem_set = 0;
    if (!smem_set) {
        cudaFuncSetAttribute(k_gemm<__half>,
                             cudaFuncAttributeMaxDynamicSharedMemorySize, GEMM_SMEM);
        smem_set = 1;
    }

    const int T = 256;
    dim3 gg(F_OUT / BN, (N_NODES + BM - 1) / BM);

    // L1: fused deg-count + x->fp16
    k_pre<<<EDGE_BLOCKS + XCVT_BLOCKS, T>>>(ei, ew, x, xh);
    // L2: dinv + warp-shuffle scan
    k_scan<<<1, 1024>>>();
    // L3: CSR scatter
    k_scatter<<<(N_EDGES + T - 1) / T, T>>>(ei, ew);
    // L4: layer-1 aggregation (fp16 -> fp16)
    k_agg_h<F_IN><<<N_NODES, F_IN / 4>>>(xh, aggh);
    // L5: weight transposes (fp32 -> fp16)
    k_tr2<<<dim3(F_OUT / 32, F_OUT / 32, 2), dim3(32, 8)>>>(W1, w1th, W2, w2th);
    // L6: gemm1 (fp16 mma, 8 warps) -> fp16 xw, bias+relu fused
    k_gemm<__half><<<gg, 256, GEMM_SMEM>>>(aggh, w1th, xw_h, b1, N_NODES, F_IN);
    // L7: layer-2 aggregation (fp16 -> fp16)
    k_agg_h<F_OUT><<<N_NODES, F_OUT / 4>>>(xw_h, aggh);
    // L8: gemm2 (fp16 mma, 8 warps) -> fp16 h2, bias+relu fused
    k_gemm<__half><<<gg, 256, GEMM_SMEM>>>(aggh, w2th, h2h, b2, N_NODES, F_OUT);
    // L9: mean pool (fp16 in) + re-zero deg/cnt
    k_pool<<<dim3(4, N_GRAPHS), 64>>>(batch, h2h, out);
}

// round 16
// speedup vs baseline: 1.0192x; 1.0033x over previous
#include <cuda_runtime.h>
#include <cuda_fp16.h>
#include <stdint.h>

#define N_NODES  20000
#define N_EDGES  320000
#define F_IN     512
#define F_OUT    1024
#define N_GRAPHS 64

// ---------------- scratch (static device globals; no allocations) ----------
__device__ float g_xw[(size_t)N_NODES * F_OUT];   // gemm1 out, fp16 [N,1024]
__device__ float g_h1[(size_t)N_NODES * F_OUT];   // agg outs, fp16 [N,512]/[N,1024]
__device__ float g_h2[(size_t)N_NODES * F_OUT];   // x fp16 early; gemm2 fp16 late
__device__ float g_w1t[(size_t)F_OUT * F_IN / 2]; // W1^T fp16 [1024,512]
__device__ float g_w2t[(size_t)F_OUT * F_OUT / 2];// W2^T fp16 [1024,1024]
__device__ float g_deg[N_NODES];                  // zero at entry (re-zeroed by pool)
__device__ float g_dinv[N_NODES];
__device__ int   g_cnt_i[N_NODES];                // zero at entry (re-zeroed by pool)
__device__ int   g_rank[N_NODES];
__device__ int   g_ptr[N_NODES + 1];
__device__ int   g_csr_src[N_EDGES];
__device__ float g_csr_norm[N_EDGES];

// ---------------- small helpers ----------------
__device__ __forceinline__ void cp_async16(uint32_t saddr, const void* gptr, bool pred) {
    int sz = pred ? 16 : 0;           // sz=0 -> zero-fill 16B
    asm volatile("cp.async.cg.shared.global [%0], [%1], 16, %2;\n"
                 :: "r"(saddr), "l"(gptr), "r"(sz));
}
#define CP_COMMIT() asm volatile("cp.async.commit_group;\n" ::)
#define CP_WAIT(n)  asm volatile("cp.async.wait_group %0;\n" :: "n"(n))

__device__ __forceinline__ void ldsm_x4(uint32_t& r0, uint32_t& r1, uint32_t& r2,
                                        uint32_t& r3, uint32_t addr) {
    asm volatile("ldmatrix.sync.aligned.m8n8.x4.shared.b16 {%0,%1,%2,%3}, [%4];"
                 : "=r"(r0), "=r"(r1), "=r"(r2), "=r"(r3) : "r"(addr));
}

// ---------------- L1: fused degree-count + x->fp16 convert ----------------
#define EDGE_BLOCKS ((N_EDGES + 255) / 256)               // 1250
#define XCVT4 (N_NODES * F_IN / 4)                        // float4 count
#define XCVT_BLOCKS ((XCVT4 + 255) / 256)                 // 10000

__global__ __launch_bounds__(256)
void k_pre(const int* __restrict__ ei, const float* __restrict__ ew,
           const float* __restrict__ x, __half* __restrict__ xh) {
    int b = blockIdx.x;
    if (b < EDGE_BLOCKS) {
        int e = b * 256 + threadIdx.x;
        if (e < N_EDGES) {
            int d = ei[N_EDGES + e];
            atomicAdd(&g_deg[d], ew[e]);
            atomicAdd(&g_cnt_i[d], 1);
        }
    } else {
        int i = (b - EDGE_BLOCKS) * 256 + threadIdx.x;
        if (i < XCVT4) {
            float4 v = ((const float4*)x)[i];
            __half2 h0 = __floats2half2_rn(v.x, v.y);
            __half2 h1 = __floats2half2_rn(v.z, v.w);
            uint2 p;
            p.x = *reinterpret_cast<uint32_t*>(&h0);
            p.y = *reinterpret_cast<uint32_t*>(&h1);
            ((uint2*)xh)[i] = p;
        }
    }
}

// L2: dinv (+1 self loop) + exclusive prefix sum -> ptr, rank (warp-shuffle)
__global__ __launch_bounds__(1024)
void k_scan() {
    __shared__ int wsum[32];
    const int CH = (N_NODES + 1023) / 1024;  // 20
    int t = threadIdx.x;
    int lane = t & 31;
    int wid  = t >> 5;
    int base = t * CH;

    int s = 0;
    #pragma unroll
    for (int i = 0; i < CH; i++) {
        int idx = base + i;
        if (idx < N_NODES) {
            float d = g_deg[idx] + 1.0f;
            g_dinv[idx] = rsqrtf(d);
            s += g_cnt_i[idx];
        }
    }

    int v = s;
    #pragma unroll
    for (int off = 1; off < 32; off <<= 1) {
        int n = __shfl_up_sync(0xffffffffu, v, off);
        if (lane >= off) v += n;
    }
    if (lane == 31) wsum[wid] = v;
    __syncthreads();
    if (wid == 0) {
        int w = (lane < 32) ? wsum[lane] : 0;
        #pragma unroll
        for (int off = 1; off < 32; off <<= 1) {
            int n = __shfl_up_sync(0xffffffffu, w, off);
            if (lane >= off) w += n;
        }
        wsum[lane] = w;
    }
    __syncthreads();
    int warp_excl = (wid > 0) ? wsum[wid - 1] : 0;
    int run = warp_excl + v - s;

    #pragma unroll
    for (int i = 0; i < CH; i++) {
        int idx = base + i;
        if (idx < N_NODES) { g_ptr[idx] = run; g_rank[idx] = run; run += g_cnt_i[idx]; }
    }
    if (t == 1023) g_ptr[N_NODES] = run;
}

// L3: CSR scatter
__global__ void k_scatter(const int* __restrict__ ei, const float* __restrict__ ew) {
    int e = blockIdx.x * blockDim.x + threadIdx.x;
    if (e < N_EDGES) {
        int s = ei[e];
        int d = ei[N_EDGES + e];
        int pos = atomicAdd(&g_rank[d], 1);
        g_csr_src[pos]  = s;
        g_csr_norm[pos] = g_dinv[s] * ew[e] * g_dinv[d];
    }
}

// ---------------- fused CSR aggregation, fp16 in -> fp16 out --------------
template<int F>
__global__ __launch_bounds__(F / 4)
void k_agg_h(const __half* __restrict__ in, __half* __restrict__ out) {
    int n = blockIdx.x;
    int f = threadIdx.x * 4;

    float di = g_dinv[n];
    float s = di * di;

    uint2 raw = *(const uint2*)(in + (size_t)n * F + f);
    float2 p0 = __half22float2(*reinterpret_cast<__half2*>(&raw.x));
    float2 p1 = __half22float2(*reinterpret_cast<__half2*>(&raw.y));
    float4 acc = make_float4(s * p0.x, s * p0.y, s * p1.x, s * p1.y);

    int e0 = g_ptr[n], e1 = g_ptr[n + 1];
    for (int e = e0; e < e1; e++) {
        int src = __ldg(&g_csr_src[e]);
        float w = __ldg(&g_csr_norm[e]);
        uint2 r = *(const uint2*)(in + (size_t)src * F + f);
        float2 u0 = __half22float2(*reinterpret_cast<__half2*>(&r.x));
        float2 u1 = __half22float2(*reinterpret_cast<__half2*>(&r.y));
        acc.x = fmaf(w, u0.x, acc.x);
        acc.y = fmaf(w, u0.y, acc.y);
        acc.z = fmaf(w, u1.x, acc.z);
        acc.w = fmaf(w, u1.y, acc.w);
    }
    __half2 o0 = __floats2half2_rn(acc.x, acc.y);
    __half2 o1 = __floats2half2_rn(acc.z, acc.w);
    uint2 p;
    p.x = *reinterpret_cast<uint32_t*>(&o0);
    p.y = *reinterpret_cast<uint32_t*>(&o1);
    *(uint2*)(out + (size_t)n * F + f) = p;
}

// ---------------- weight transposes (fp32 -> fp16) ----------------
__device__ __forceinline__ void tr_tile(const float* __restrict__ W,
                                        __half* __restrict__ Wt, int R, int C) {
    __shared__ float s[32][33];
    int x  = blockIdx.x * 32 + threadIdx.x;
    int y0 = blockIdx.y * 32;
    #pragma unroll
    for (int i = 0; i < 32; i += 8)
        s[threadIdx.y + i][threadIdx.x] = W[(size_t)(y0 + threadIdx.y + i) * C + x];
    __syncthreads();
    int xt  = blockIdx.y * 32 + threadIdx.x;
    int yt0 = blockIdx.x * 32;
    #pragma unroll
    for (int i = 0; i < 32; i += 8)
        Wt[(size_t)(yt0 + threadIdx.y + i) * R + xt] = __float2half_rn(s[threadIdx.x][threadIdx.y + i]);
}

__global__ __launch_bounds__(256)
void k_tr2(const float* __restrict__ W1, __half* __restrict__ W1t,
           const float* __restrict__ W2, __half* __restrict__ W2t) {
    if (blockIdx.z == 0) {
        if (blockIdx.y < F_IN / 32) tr_tile(W1, W1t, F_IN, F_OUT);
    } else {
        tr_tile(W2, W2t, F_OUT, F_OUT);
    }
}

// ---------------- fp16 mma.sync GEMM, persistent CTAs --------------------
// C = relu(A @ W + bias); A fp16 [M,K], Bt = W^T fp16 [1024,K] row-major.
// R13 inner loop: 128x128 tile, BK=64, 4 warps 2x2 (64x64), 3-stage cp.async,
// 2 CTAs/SM. Persistent: 296 CTAs loop over tiles; next tile's 2-stage
// prologue fill overlaps the current tile's (register-only) epilogue.
#define BM 128
#define BN 128
#define BKH 64                                // K halfs per stage
#define PADH 72                               // halfs per smem row (144B)
#define A_STG (BM * PADH)
#define B_STG (BN * PADH)
#define GEMM_SMEM (3 * (A_STG + B_STG) * 2)   // 110592 B
#define NTILE_N (F_OUT / BN)                  // 8
#define M_TILES ((N_NODES + BM - 1) / BM)     // 157
#define NTILES (M_TILES * NTILE_N)            // 1256
#define GEMM_GRID 296                         // 148 SMs x 2 CTAs

__device__ __forceinline__ void mma_f16(float c[4], const uint32_t a[4],
                                        uint32_t b0, uint32_t b1) {
    asm volatile(
        "mma.sync.aligned.m16n8k16.row.col.f32.f16.f16.f32 "
        "{%0,%1,%2,%3}, {%4,%5,%6,%7}, {%8,%9}, {%0,%1,%2,%3};"
        : "+f"(c[0]), "+f"(c[1]), "+f"(c[2]), "+f"(c[3])
        : "r"(a[0]), "r"(a[1]), "r"(a[2]), "r"(a[3]), "r"(b0), "r"(b1));
}

__global__ __launch_bounds__(128, 2)
void k_gemm(const __half* __restrict__ A, const __half* __restrict__ Bt,
            __half* __restrict__ C, const float* __restrict__ bias, int M, int K) {
    extern __shared__ __half smem[];

    const int tid  = threadIdx.x;
    const int lane = tid & 31;
    const int warp = tid >> 5;
    const int wm = warp & 1;
    const int wn = warp >> 1;
    const int g = lane >> 2;
    const int t = lane & 3;

    uint32_t sbase = (uint32_t)__cvta_generic_to_shared(smem);
    uint32_t sA[3], sB[3];
    #pragma unroll
    for (int s = 0; s < 3; s++) {
        sA[s] = sbase + (uint32_t)(s * (A_STG + B_STG)) * 2;
        sB[s] = sA[s] + A_STG * 2;
    }

    const int la_row = wm * 64 + ((lane >> 3) & 1) * 8 + (lane & 7);
    const int la_col = ((lane >> 4) & 1) * 8;   // halfs
    const int lb_row = wn * 64 + ((lane >> 4) & 1) * 8 + (lane & 7);
    const int lb_col = ((lane >> 3) & 1) * 8;   // halfs

    const int KT = K >> 6;   // k-tiles of 64 halfs

    // fill one stage for tile at (Ag_, Bg_, rmaxA_)
    #define FILL(st, kt_, Ag_, Bg_, rmaxA_) do {                                 \
        int k0_ = (kt_) * BKH;                                                   \
        _Pragma("unroll")                                                        \
        for (int u_ = 0; u_ < 8; u_++) {                                         \
            int ch_ = tid + u_ * 128;                                            \
            int r_ = ch_ >> 3, c_ = ch_ & 7;                                     \
            cp_async16(sA[st] + (r_ * PADH + c_ * 8) * 2,                        \
                       (Ag_) + (size_t)r_ * K + k0_ + c_ * 8, r_ < (rmaxA_));    \
            cp_async16(sB[st] + (r_ * PADH + c_ * 8) * 2,                        \
                       (Bg_) + (size_t)r_ * K + k0_ + c_ * 8, true);             \
        }                                                                        \
        CP_COMMIT();                                                             \
    } while (0)

    int tile = blockIdx.x;
    if (tile >= NTILES) return;

    int brow = (tile >> 3) * BM;
    int bcol = (tile & 7) * BN;
    const __half* Ag = A + (size_t)brow * K;
    const __half* Bg = Bt + (size_t)bcol * K;
    int rmaxA = M - brow;

    // prologue for first tile
    FILL(0, 0, Ag, Bg, rmaxA);
    FILL(1, 1, Ag, Bg, rmaxA);

    while (true) {
        float acc[4][8][4];
        #pragma unroll
        for (int i = 0; i < 4; i++)
            #pragma unroll
            for (int j = 0; j < 8; j++)
                #pragma unroll
                for (int r = 0; r < 4; r++) acc[i][j][r] = 0.0f;

        for (int kt = 0; kt < KT; kt++) {
            if (kt + 1 < KT) { CP_WAIT(1); } else { CP_WAIT(0); }
            __syncthreads();

            // hoist next fill: stage (kt+2)%3 == (kt-1)%3, free after barrier
            if (kt + 2 < KT) {
                int nb = (kt + 2) % 3;
                FILL(nb, kt + 2, Ag, Bg, rmaxA);
            }

            int buf = kt % 3;
            uint32_t aab = sA[buf] + (la_row * PADH + la_col) * 2;
            uint32_t bab = sB[buf] + (lb_row * PADH + lb_col) * 2;

            #pragma unroll
            for (int ks = 0; ks < 4; ks++) {
                const int kb = ks * 16;   // halfs
                uint32_t af[4][4];
                #pragma unroll
                for (int i = 0; i < 4; i++)
                    ldsm_x4(af[i][0], af[i][1], af[i][2], af[i][3],
                            aab + (i * 16 * PADH + kb) * 2);
                uint32_t bf[4][4];
                #pragma unroll
                for (int j2 = 0; j2 < 4; j2++)
                    ldsm_x4(bf[j2][0], bf[j2][1], bf[j2][2], bf[j2][3],
                            bab + (j2 * 16 * PADH + kb) * 2);
                #pragma unroll
                for (int i = 0; i < 4; i++) {
                    #pragma unroll
                    for (int j = 0; j < 8; j++) {
                        const uint32_t* bp = &bf[j >> 1][(j & 1) * 2];
                        mma_f16(acc[i][j], af[i], bp[0], bp[1]);
                    }
                }
            }
        }

        // all warps finished reading smem for this tile
        __syncthreads();

        // issue next tile's 2-stage prologue (overlaps epilogue below)
        int ntile = tile + GEMM_GRID;
        int nbrow = 0, nbcol = 0, nrmax = 0;
        const __half *nAg = nullptr, *nBg = nullptr;
        bool have_next = (ntile < NTILES);
        if (have_next) {
            nbrow = (ntile >> 3) * BM;
            nbcol = (ntile & 7) * BN;
            nAg = A + (size_t)nbrow * K;
            nBg = Bt + (size_t)nbcol * K;
            nrmax = M - nbrow;
            FILL(0, 0, nAg, nBg, nrmax);
            FILL(1, 1, nAg, nBg, nrmax);
        }

        // epilogue (registers only): bias + relu, fp16 store
        #pragma unroll
        for (int j = 0; j < 8; j++) {
            int c0 = bcol + wn * 64 + j * 8 + 2 * t;
            float2 bb = *(const float2*)(bias + c0);
            #pragma unroll
            for (int i = 0; i < 4; i++) {
                int r0 = brow + wm * 64 + i * 16 + g;
                int r1 = r0 + 8;
                if (r0 < M) {
                    __half2 h = __floats2half2_rn(fmaxf(acc[i][j][0] + bb.x, 0.0f),
                                                  fmaxf(acc[i][j][1] + bb.y, 0.0f));
                    *(uint32_t*)(C + (size_t)r0 * F_OUT + c0) =
                        *reinterpret_cast<uint32_t*>(&h);
                }
                if (r1 < M) {
                    __half2 h = __floats2half2_rn(fmaxf(acc[i][j][2] + bb.x, 0.0f),
                                                  fmaxf(acc[i][j][3] + bb.y, 0.0f));
                    *(uint32_t*)(C + (size_t)r1 * F_OUT + c0) =
                        *reinterpret_cast<uint32_t*>(&h);
                }
            }
        }

        if (!have_next) break;
        tile = ntile; brow = nbrow; bcol = nbcol;
        Ag = nAg; Bg = nBg; rmaxA = nrmax;
    }
    #undef FILL
}

// ---------------- segmented mean pooling (fp16 in) + re-zero deg/cnt -----
__global__ __launch_bounds__(64)
void k_pool(const int* __restrict__ batch, const __half* __restrict__ h,
            float* __restrict__ out) {
    int gph = blockIdx.y;
    int f = blockIdx.x * 256 + threadIdx.x * 4;

    int gt = (blockIdx.y * gridDim.x + blockIdx.x) * 64 + threadIdx.x;
    for (int i = gt; i < N_NODES; i += 16384) { g_deg[i] = 0.0f; g_cnt_i[i] = 0; }

    int lo = 0, hi = N_NODES;
    while (lo < hi) { int m = (lo + hi) >> 1; if (batch[m] < gph) lo = m + 1; else hi = m; }
    int s = lo;
    hi = N_NODES;
    while (lo < hi) { int m = (lo + hi) >> 1; if (batch[m] < gph + 1) lo = m + 1; else hi = m; }
    int e = lo;

    float4 acc = make_float4(0.f, 0.f, 0.f, 0.f);
    for (int n = s; n < e; n++) {
        uint2 r = *(const uint2*)(h + (size_t)n * F_OUT + f);
        float2 u0 = __half22float2(*reinterpret_cast<__half2*>(&r.x));
        float2 u1 = __half22float2(*reinterpret_cast<__half2*>(&r.y));
        acc.x += u0.x; acc.y += u0.y; acc.z += u1.x; acc.w += u1.y;
    }
    float c = 1.0f / fmaxf((float)(e - s), 1.0f);
    acc.x *= c; acc.y *= c; acc.z *= c; acc.w *= c;
    *(float4*)(out + (size_t)gph * F_OUT + f) = acc;
}

// ---------------- launch ----------------
extern "C" void kernel_launch(void* const* d_in, const int* in_sizes, int n_in,
                              void* d_out, int out_size) {
    const float* x     = (const float*)d_in[0];
    const int*   ei    = (const int*)d_in[1];
    const float* ew    = (const float*)d_in[2];
    const int*   batch = (const int*)d_in[3];
    const float* W1    = (const float*)d_in[4];
    const float* b1    = (const float*)d_in[5];
    const float* W2    = (const float*)d_in[6];
    const float* b2    = (const float*)d_in[7];
    float* out = (float*)d_out;

    float *xw, *h1, *h2, *w1t, *w2t;
    cudaGetSymbolAddress((void**)&xw,  g_xw);
    cudaGetSymbolAddress((void**)&h1,  g_h1);
    cudaGetSymbolAddress((void**)&h2,  g_h2);
    cudaGetSymbolAddress((void**)&w1t, g_w1t);
    cudaGetSymbolAddress((void**)&w2t, g_w2t);

    __half* xh    = (__half*)h2;
    __half* aggh  = (__half*)h1;
    __half* xw_h  = (__half*)xw;
    __half* h2h   = (__half*)h2;     // gemm2 fp16 output (xh dead by then)
    __half* w1th  = (__half*)w1t;
    __half* w2th  = (__half*)w2t;

    static int smem_set = 0;
    if (!smem_set) {
        cudaFuncSetAttribute(k_gemm,
                             cudaFuncAttributeMaxDynamicSharedMemorySize, GEMM_SMEM);
        smem_set = 1;
    }

    const int T = 256;

    // L1: fused deg-count + x->fp16
    k_pre<<<EDGE_BLOCKS + XCVT_BLOCKS, T>>>(ei, ew, x, xh);
    // L2: dinv + warp-shuffle scan
    k_scan<<<1, 1024>>>();
    // L3: CSR scatter
    k_scatter<<<(N_EDGES + T - 1) / T, T>>>(ei, ew);
    // L4: layer-1 aggregation (fp16 -> fp16)
    k_agg_h<F_IN><<<N_NODES, F_IN / 4>>>(xh, aggh);
    // L5: weight transposes (fp32 -> fp16)
    k_tr2<<<dim3(F_OUT / 32, F_OUT / 32, 2), dim3(32, 8)>>>(W1, w1th, W2, w2th);
    // L6: gemm1 (persistent) -> fp16 xw, bias+relu fused
    k_gemm<<<GEMM_GRID, 128, GEMM_SMEM>>>(aggh, w1th, xw_h, b1, N_NODES, F_IN);
    // L7: layer-2 aggregation (fp16 -> fp16)
    k_agg_h<F_OUT><<<N_NODES, F_OUT / 4>>>(xw_h, aggh);
    // L8: gemm2 (persistent) -> fp16 h2, bias+relu fused
    k_gemm<<<GEMM_GRID, 128, GEMM_SMEM>>>(aggh, w2th, h2h, b2, N_NODES, F_OUT);
    // L9: mean pool (fp16 in) + re-zero deg/cnt
    k_pool<<<dim3(4, N_GRAPHS), 64>>>(batch, h2h, out);
}